// round 13
// baseline (speedup 1.0000x reference)
#include <cuda_runtime.h>
#include <cuda_fp16.h>
#include <cstdint>

#define NTHR  640     // 512 consumer + 128 producer
#define NCONS 512
#define ET    128
#define XSTR  264     // halves
#define W1STR 136
#define W2STR 96
#define HSTR  136
#define MSTR  100     // fp16 message stride (halves)
#define MOFF  34816   // byte offset of sM inside X buffer (above H region)
// byte offsets in dynamic smem
#define B_X0  0            // 67584
#define B_X1  67584        // 67584
#define B_W1  135168       // 69632
#define B_W2  204800       // 24576
#define B_DST 229376       // 1024
#define B_B1  230400       // 512
#define B_B2  230912       // 384+pad
#define SMEMB 231424

// named barrier ids: FULL0=1 FULL1=2 EMPTY0=3 EMPTY1=4 C1=5 C2=6
#define BAR_SYNC(id, cnt)   asm volatile("bar.sync %0, %1;"   :: "r"(id), "r"(cnt) : "memory")
#define BAR_ARRIVE(id, cnt) asm volatile("bar.arrive %0, %1;" :: "r"(id), "r"(cnt) : "memory")

__device__ __forceinline__ uint32_t s2u(const void* p) {
    uint32_t a; asm("{ .reg .u64 t; cvta.to.shared.u64 t, %1; cvt.u32.u64 %0, t; }" : "=r"(a) : "l"(p)); return a;
}
__device__ __forceinline__ void ldsm4(uint32_t a, uint32_t& r0, uint32_t& r1, uint32_t& r2, uint32_t& r3) {
    asm volatile("ldmatrix.sync.aligned.m8n8.x4.shared.b16 {%0,%1,%2,%3}, [%4];"
                 : "=r"(r0), "=r"(r1), "=r"(r2), "=r"(r3) : "r"(a));
}
__device__ __forceinline__ void ldsm4t(uint32_t a, uint32_t& r0, uint32_t& r1, uint32_t& r2, uint32_t& r3) {
    asm volatile("ldmatrix.sync.aligned.m8n8.x4.trans.shared.b16 {%0,%1,%2,%3}, [%4];"
                 : "=r"(r0), "=r"(r1), "=r"(r2), "=r"(r3) : "r"(a));
}
__device__ __forceinline__ void ldsm2t(uint32_t a, uint32_t& r0, uint32_t& r1) {
    asm volatile("ldmatrix.sync.aligned.m8n8.x2.trans.shared.b16 {%0,%1}, [%2];"
                 : "=r"(r0), "=r"(r1) : "r"(a));
}
__device__ __forceinline__ void stsm4(uint32_t a, uint32_t r0, uint32_t r1, uint32_t r2, uint32_t r3) {
    asm volatile("stmatrix.sync.aligned.m8n8.x4.shared.b16 [%0], {%1,%2,%3,%4};"
                 :: "r"(a), "r"(r0), "r"(r1), "r"(r2), "r"(r3) : "memory");
}
__device__ __forceinline__ void mma16816(float* c, const uint32_t* a, const uint32_t* b) {
    asm volatile("mma.sync.aligned.m16n8k16.row.col.f32.f16.f16.f32 "
                 "{%0,%1,%2,%3}, {%4,%5,%6,%7}, {%8,%9}, {%0,%1,%2,%3};"
                 : "+f"(c[0]), "+f"(c[1]), "+f"(c[2]), "+f"(c[3])
                 : "r"(a[0]), "r"(a[1]), "r"(a[2]), "r"(a[3]), "r"(b[0]), "r"(b[1]));
}
__device__ __forceinline__ void red4(float* p, float a, float b, float c, float d) {
    asm volatile("red.global.add.v4.f32 [%0], {%1,%2,%3,%4};"
                 :: "l"(p), "f"(a), "f"(b), "f"(c), "f"(d) : "memory");
}
// 8 fp32 -> 8 fp16, one 16B STS
__device__ __forceinline__ void wr8h(__half* px, int idx, const float* v) {
    uint4 u;
    uint32_t* w = (uint32_t*)&u;
    #pragma unroll
    for (int q = 0; q < 4; q++) {
        __half h0 = __float2half_rn(v[2*q]), h1 = __float2half_rn(v[2*q+1]);
        w[q] = (uint32_t)__half_as_ushort(h0) | ((uint32_t)__half_as_ushort(h1) << 16);
    }
    *(uint4*)(px + idx) = u;
}
// inverse-rotate one rep (8 values)
__device__ __forceinline__ void rot8(const float* p, const float4* rk, float* o) {
    #pragma unroll
    for (int k = 0; k < 4; k++) {
        float x0 = p[2*k], x1 = p[2*k+1];
        o[2*k]   = x0 * rk[k].x + x1 * rk[k].y;
        o[2*k+1] = x0 * rk[k].z + x1 * rk[k].w;
    }
}

__global__ __launch_bounds__(NTHR, 1)
void eq_main(const float* __restrict__ xs, const float* __restrict__ xr,
             const int* __restrict__ ei, const float* __restrict__ dist,
             const float* __restrict__ rot,
             const float* __restrict__ W1, const float* __restrict__ b1,
             const float* __restrict__ W2, const float* __restrict__ b2,
             float* __restrict__ outS, float* __restrict__ outR,
             int E, int n_tiles)
{
    extern __shared__ __align__(16) unsigned char dyn[];
    const uint32_t sb = s2u(dyn);
    __half* sW1 = (__half*)(dyn + B_W1);
    __half* sW2 = (__half*)(dyn + B_W2);
    int*   sDst = (int*)  (dyn + B_DST);
    float* sB1  = (float*)(dyn + B_B1);
    float* sB2  = (float*)(dyn + B_B2);

    const int tid = threadIdx.x, lane = tid & 31, wid = tid >> 5;

    // ---- stage weights + biases once (all threads) ----
    for (int i = tid; i < 256 * 128; i += NTHR) {
        int k = i >> 7, n = i & 127;
        sW1[k * W1STR + n] = __float2half_rn(W1[i]);
    }
    for (int i = tid; i < 128 * 96; i += NTHR) {
        int k = i / 96, n = i - k * 96;
        sW2[k * W2STR + n] = __float2half_rn(W2[i]);
    }
    if (tid < 128) sB1[tid] = b1[tid];
    else if (tid < 224) sB2[tid - 128] = b2[tid - 128];
    __syncthreads();

    const int t0 = blockIdx.x, gstride = gridDim.x;

    if (wid >= 16) {
        // ========= PRODUCER: 4 warps, 4 threads/edge, 4 passes of 32 edges =========
        const int ptid = tid - NCONS;    // 0..127
        const int pe0  = ptid >> 2;      // 0..31
        const int s    = ptid & 3;       // quarter 0..3
        int i = 0;
        for (int t = t0; t < n_tiles; t += gstride, i++) {
            const int buf = i & 1;
            if (i >= 2) BAR_SYNC(3 + buf, NTHR);        // wait EMPTY[buf]
            __half* X = (__half*)(dyn + (buf ? B_X1 : B_X0));
            const int base = t * ET;
            #pragma unroll
            for (int pass = 0; pass < 4; pass++) {
                const int pe = pass * 32 + pe0;
                const int e  = base + pe;
                const int ec = (e < E) ? e : (E - 1);
                const int srcn = ei[ec], dstn = ei[E + ec];
                if (s == 0) sDst[buf * ET + pe] = dstn;
                float4 rk[4];
                #pragma unroll
                for (int k = 0; k < 4; k++) rk[k] = *(const float4*)(rot + (size_t)ec * 16 + k * 4);
                const int rb = pe * XSTR;
                float tmp[8], in[8];
                *(float4*)(tmp)     = *(const float4*)(xs + (size_t)dstn * 32 + s * 8);
                *(float4*)(tmp + 4) = *(const float4*)(xs + (size_t)dstn * 32 + s * 8 + 4);
                wr8h(X, rb + s * 8, tmp);
                *(float4*)(tmp)     = *(const float4*)(xs + (size_t)srcn * 32 + s * 8);
                *(float4*)(tmp + 4) = *(const float4*)(xs + (size_t)srcn * 32 + s * 8 + 4);
                wr8h(X, rb + 96 + s * 8, tmp);
                #pragma unroll
                for (int jj = 0; jj < 2; jj++) {
                    const int j = 2 * s + jj;
                    *(float4*)(in)     = *(const float4*)(xr + (size_t)dstn * 64 + j * 8);
                    *(float4*)(in + 4) = *(const float4*)(xr + (size_t)dstn * 64 + j * 8 + 4);
                    rot8(in, rk, tmp);
                    wr8h(X, rb + 32 + j * 8, tmp);
                    *(float4*)(in)     = *(const float4*)(xr + (size_t)srcn * 64 + j * 8);
                    *(float4*)(in + 4) = *(const float4*)(xr + (size_t)srcn * 64 + j * 8 + 4);
                    rot8(in, rk, tmp);
                    wr8h(X, rb + 128 + j * 8, tmp);
                }
                *(float4*)(tmp)     = *(const float4*)(dist + (size_t)ec * 64 + s * 16);
                *(float4*)(tmp + 4) = *(const float4*)(dist + (size_t)ec * 64 + s * 16 + 4);
                wr8h(X, rb + 192 + s * 16, tmp);
                *(float4*)(tmp)     = *(const float4*)(dist + (size_t)ec * 64 + s * 16 + 8);
                *(float4*)(tmp + 4) = *(const float4*)(dist + (size_t)ec * 64 + s * 16 + 12);
                wr8h(X, rb + 200 + s * 16, tmp);
            }
            BAR_ARRIVE(1 + buf, NTHR);                  // signal FULL[buf]
        }
    } else {
        // ================= CONSUMER: 16 warps, warp tile 32 x 32 =================
        const int mw = wid >> 2, nw = wid & 3;
        const int lr = lane & 15, lc = (lane >> 4) << 3;
        const int g  = lane >> 2, tc = (lane & 3) * 2;
        const uint32_t w1B = sb + B_W1, w2B = sb + B_W2;
        const int c0   = nw * 24 + tc;
        const int kfix = (((c0 >= 32 ? c0 : c0 + 24) - 32) >> 1) & 3;

        int i = 0;
        for (int t = t0; t < n_tiles; t += gstride, i++) {
            const int buf = i & 1;
            const int base = t * ET;
            const uint32_t xB = sb + (buf ? B_X1 : B_X0);

            BAR_SYNC(1 + buf, NTHR);                    // wait FULL[buf]

            // ---------- GEMM1: 128 x 128 x 256 ----------
            float acc[2][4][4] = {};
            #pragma unroll 2
            for (int ks = 0; ks < 16; ks++) {
                const int k0 = ks * 16;
                uint32_t b[4][2];
                ldsm4t(w1B + (uint32_t)(((k0 + lr) * W1STR + nw * 32 + lc) * 2),
                       b[0][0], b[0][1], b[1][0], b[1][1]);
                ldsm4t(w1B + (uint32_t)(((k0 + lr) * W1STR + nw * 32 + 16 + lc) * 2),
                       b[2][0], b[2][1], b[3][0], b[3][1]);
                uint32_t A[2][4];
                #pragma unroll
                for (int mi = 0; mi < 2; mi++)
                    ldsm4(xB + (uint32_t)(((mw * 32 + mi * 16 + lr) * XSTR + k0 + lc) * 2),
                          A[mi][0], A[mi][1], A[mi][2], A[mi][3]);
                #pragma unroll
                for (int mi = 0; mi < 2; mi++)
                    #pragma unroll
                    for (int nt = 0; nt < 4; nt++)
                        mma16816(acc[mi][nt], A[mi], b[nt]);
            }
            BAR_SYNC(5, NCONS);                         // G1 reads of X[buf] done

            // ---------- epilogue1: bias + silu -> H via stmatrix ----------
            {
                const uint32_t hB = xB;   // H overlays X[buf]
                const int tsel = lane >> 3, rowin = lane & 7;
                #pragma unroll
                for (int mi = 0; mi < 2; mi++) {
                    uint32_t pk[4][2];
                    #pragma unroll
                    for (int ni = 0; ni < 4; ni++) {
                        const int c = nw * 32 + ni * 8 + tc;
                        float2 bb = *(const float2*)(sB1 + c);
                        float v[4];
                        v[0] = acc[mi][ni][0] + bb.x;  v[1] = acc[mi][ni][1] + bb.y;
                        v[2] = acc[mi][ni][2] + bb.x;  v[3] = acc[mi][ni][3] + bb.y;
                        #pragma unroll
                        for (int q = 0; q < 4; q++) v[q] = v[q] / (1.f + __expf(-v[q]));
                        __half h0 = __float2half_rn(v[0]), h1 = __float2half_rn(v[1]);
                        __half h2 = __float2half_rn(v[2]), h3 = __float2half_rn(v[3]);
                        pk[ni][0] = (uint32_t)__half_as_ushort(h0) | ((uint32_t)__half_as_ushort(h1) << 16);
                        pk[ni][1] = (uint32_t)__half_as_ushort(h2) | ((uint32_t)__half_as_ushort(h3) << 16);
                    }
                    #pragma unroll
                    for (int np = 0; np < 2; np++) {
                        const int ni_t = np * 2 + (tsel >> 1);
                        const int rh_t = tsel & 1;
                        const int row  = mw * 32 + mi * 16 + rh_t * 8 + rowin;
                        const int col  = nw * 32 + ni_t * 8;
                        uint32_t addr = hB + (uint32_t)((row * HSTR + col) * 2);
                        stsm4(addr, pk[np*2][0], pk[np*2][1], pk[np*2+1][0], pk[np*2+1][1]);
                    }
                }
            }
            BAR_SYNC(6, NCONS);                         // H visible

            // ---------- GEMM2: 128 x 96 x 128 ----------
            float acc2[2][3][4] = {};
            #pragma unroll 2
            for (int ks = 0; ks < 8; ks++) {
                const int k0 = ks * 16;
                uint32_t b[3][2];
                ldsm4t(w2B + (uint32_t)(((k0 + lr) * W2STR + nw * 24 + lc) * 2),
                       b[0][0], b[0][1], b[1][0], b[1][1]);
                ldsm2t(w2B + (uint32_t)(((k0 + lr) * W2STR + nw * 24 + 16) * 2),
                       b[2][0], b[2][1]);
                uint32_t A[2][4];
                #pragma unroll
                for (int mi = 0; mi < 2; mi++)
                    ldsm4(xB + (uint32_t)(((mw * 32 + mi * 16 + lr) * HSTR + k0 + lc) * 2),
                          A[mi][0], A[mi][1], A[mi][2], A[mi][3]);
                #pragma unroll
                for (int mi = 0; mi < 2; mi++)
                    #pragma unroll
                    for (int nt = 0; nt < 3; nt++)
                        mma16816(acc2[mi][nt], A[mi], b[nt]);
            }

            // ---------- epilogue2a: bias + rotate -> fp16 sM (disjoint from H; no bar) ----
            {
                __half* sM = (__half*)(dyn + (buf ? B_X1 : B_X0) + MOFF);
                #pragma unroll
                for (int mi = 0; mi < 2; mi++) {
                    const int rr = mw * 32 + mi * 16 + g;
                    #pragma unroll
                    for (int rh = 0; rh < 2; rh++) {
                        const int r = rr + rh * 8;
                        const int e = base + r;
                        const int ec = (e < E) ? e : (E - 1);
                        float4 R;
                        if (c0 + 16 >= 32)
                            R = *(const float4*)(rot + (size_t)ec * 16 + kfix * 4);
                        #pragma unroll
                        for (int ni = 0; ni < 3; ni++) {
                            const int c = nw * 24 + ni * 8 + tc;
                            float2 bb = *(const float2*)(sB2 + c);
                            float m0 = acc2[mi][ni][rh*2]   + bb.x;
                            float m1 = acc2[mi][ni][rh*2+1] + bb.y;
                            float v0, v1;
                            if (c < 32) { v0 = m0; v1 = m1; }
                            else {
                                v0 = m0 * R.x + m1 * R.z;
                                v1 = m0 * R.y + m1 * R.w;
                            }
                            __half h0 = __float2half_rn(v0), h1 = __float2half_rn(v1);
                            *(uint32_t*)(sM + r * MSTR + c) =
                                (uint32_t)__half_as_ushort(h0) | ((uint32_t)__half_as_ushort(h1) << 16);
                        }
                    }
                }
            }
            BAR_SYNC(6, NCONS);                         // sM staged (all warps)

            // ---------- epilogue2b: coalesced fp16->fp32 scatter ----------
            {
                const __half* sM = (const __half*)(dyn + (buf ? B_X1 : B_X0) + MOFF);
                #pragma unroll
                for (int it = 0; it < 6; it++) {
                    const int q  = tid + it * NCONS;    // 0..3071 = 128 edges * 24 groups
                    const int eL = q / 24;
                    const int c4 = q - eL * 24;
                    const int e  = base + eL;
                    if (e < E) {
                        const int nidx = sDst[buf * ET + eL];
                        const __half2* mp = (const __half2*)(sM + eL * MSTR + c4 * 4);
                        float2 fa = __half22float2(mp[0]);
                        float2 fb = __half22float2(mp[1]);
                        if (c4 < 8)
                            red4(outS + (size_t)nidx * 32 + c4 * 4, fa.x, fa.y, fb.x, fb.y);
                        else
                            red4(outR + (size_t)nidx * 64 + (c4 - 8) * 4, fa.x, fa.y, fb.x, fb.y);
                    }
                }
            }
            BAR_ARRIVE(3 + buf, NTHR);                  // release EMPTY[buf]
        }
    }
}

extern "C" void kernel_launch(void* const* d_in, const int* in_sizes, int n_in,
                              void* d_out, int out_size)
{
    const float* xs   = (const float*)d_in[0];
    const float* xr   = (const float*)d_in[1];
    const int*   ei   = (const int*)  d_in[2];
    const float* dist = (const float*)d_in[3];
    const float* rot  = (const float*)d_in[4];
    const float* W1   = (const float*)d_in[5];
    const float* b1   = (const float*)d_in[6];
    const float* W2   = (const float*)d_in[7];
    const float* b2   = (const float*)d_in[8];

    const int N = in_sizes[0] / 32;
    const int E = in_sizes[2] / 2;
    const int n_tiles = (E + ET - 1) / ET;

    float* outS = (float*)d_out;
    float* outR = outS + (size_t)N * 32;

    cudaMemsetAsync(d_out, 0, (size_t)out_size * sizeof(float), 0);
    cudaFuncSetAttribute(eq_main, cudaFuncAttributeMaxDynamicSharedMemorySize, SMEMB);
    int grid = n_tiles < 148 ? n_tiles : 148;
    eq_main<<<grid, NTHR, SMEMB>>>(xs, xr, ei, dist, rot, W1, b1, W2, b2,
                                   outS, outR, E, n_tiles);
}

// round 14
// speedup vs baseline: 1.0527x; 1.0527x over previous
#include <cuda_runtime.h>
#include <cuda_fp16.h>
#include <cstdint>

#define NTHR  640     // 2 groups x (256 consumer + 64 producer)
#define ET    64      // edges per tile (per group)
#define XSTR  264     // halves
#define W1STR 136
#define W2STR 96
#define HSTR  136
#define XBUFB 33792   // bytes per X buffer (64*264*2)
// byte offsets in dynamic smem
#define B_X   0            // 4 buffers: grp*67584 + buf*33792
#define B_W1  135168       // 69632
#define B_W2  204800       // 24576
#define B_DST 229376       // 1024: grp*512 + buf*256
#define B_B1  230400       // 512
#define B_B2  230912       // 384+pad
#define SMEMB 231424

#define BAR_SYNC(id, cnt)   asm volatile("bar.sync %0, %1;"   :: "r"(id), "r"(cnt) : "memory")
#define BAR_ARRIVE(id, cnt) asm volatile("bar.arrive %0, %1;" :: "r"(id), "r"(cnt) : "memory")

__device__ __forceinline__ uint32_t s2u(const void* p) {
    uint32_t a; asm("{ .reg .u64 t; cvta.to.shared.u64 t, %1; cvt.u32.u64 %0, t; }" : "=r"(a) : "l"(p)); return a;
}
__device__ __forceinline__ void ldsm4(uint32_t a, uint32_t& r0, uint32_t& r1, uint32_t& r2, uint32_t& r3) {
    asm volatile("ldmatrix.sync.aligned.m8n8.x4.shared.b16 {%0,%1,%2,%3}, [%4];"
                 : "=r"(r0), "=r"(r1), "=r"(r2), "=r"(r3) : "r"(a));
}
__device__ __forceinline__ void ldsm4t(uint32_t a, uint32_t& r0, uint32_t& r1, uint32_t& r2, uint32_t& r3) {
    asm volatile("ldmatrix.sync.aligned.m8n8.x4.trans.shared.b16 {%0,%1,%2,%3}, [%4];"
                 : "=r"(r0), "=r"(r1), "=r"(r2), "=r"(r3) : "r"(a));
}
__device__ __forceinline__ void ldsm2t(uint32_t a, uint32_t& r0, uint32_t& r1) {
    asm volatile("ldmatrix.sync.aligned.m8n8.x2.trans.shared.b16 {%0,%1}, [%2];"
                 : "=r"(r0), "=r"(r1) : "r"(a));
}
__device__ __forceinline__ void stsm4(uint32_t a, uint32_t r0, uint32_t r1, uint32_t r2, uint32_t r3) {
    asm volatile("stmatrix.sync.aligned.m8n8.x4.shared.b16 [%0], {%1,%2,%3,%4};"
                 :: "r"(a), "r"(r0), "r"(r1), "r"(r2), "r"(r3) : "memory");
}
__device__ __forceinline__ void mma16816(float* c, const uint32_t* a, const uint32_t* b) {
    asm volatile("mma.sync.aligned.m16n8k16.row.col.f32.f16.f16.f32 "
                 "{%0,%1,%2,%3}, {%4,%5,%6,%7}, {%8,%9}, {%0,%1,%2,%3};"
                 : "+f"(c[0]), "+f"(c[1]), "+f"(c[2]), "+f"(c[3])
                 : "r"(a[0]), "r"(a[1]), "r"(a[2]), "r"(a[3]), "r"(b[0]), "r"(b[1]));
}
__device__ __forceinline__ void red2(float* p, float a, float b) {
    asm volatile("red.global.add.v2.f32 [%0], {%1,%2};" :: "l"(p), "f"(a), "f"(b) : "memory");
}
// 8 fp32 -> 8 fp16, one 16B STS
__device__ __forceinline__ void wr8h(__half* px, int idx, const float* v) {
    uint4 u;
    uint32_t* w = (uint32_t*)&u;
    #pragma unroll
    for (int q = 0; q < 4; q++) {
        __half h0 = __float2half_rn(v[2*q]), h1 = __float2half_rn(v[2*q+1]);
        w[q] = (uint32_t)__half_as_ushort(h0) | ((uint32_t)__half_as_ushort(h1) << 16);
    }
    *(uint4*)(px + idx) = u;
}
// inverse-rotate one rep (8 values)
__device__ __forceinline__ void rot8(const float* p, const float4* rk, float* o) {
    #pragma unroll
    for (int k = 0; k < 4; k++) {
        float x0 = p[2*k], x1 = p[2*k+1];
        o[2*k]   = x0 * rk[k].x + x1 * rk[k].y;
        o[2*k+1] = x0 * rk[k].z + x1 * rk[k].w;
    }
}

__global__ __launch_bounds__(NTHR, 1)
void eq_main(const float* __restrict__ xs, const float* __restrict__ xr,
             const int* __restrict__ ei, const float* __restrict__ dist,
             const float* __restrict__ rot,
             const float* __restrict__ W1, const float* __restrict__ b1,
             const float* __restrict__ W2, const float* __restrict__ b2,
             float* __restrict__ outS, float* __restrict__ outR,
             int E, int n_tiles)
{
    extern __shared__ __align__(16) unsigned char dyn[];
    const uint32_t sb = s2u(dyn);
    __half* sW1 = (__half*)(dyn + B_W1);
    __half* sW2 = (__half*)(dyn + B_W2);
    int*   sDst = (int*)  (dyn + B_DST);
    float* sB1  = (float*)(dyn + B_B1);
    float* sB2  = (float*)(dyn + B_B2);

    const int tid = threadIdx.x, lane = tid & 31, wid = tid >> 5;

    // ---- stage weights + biases once (all threads) ----
    for (int i = tid; i < 256 * 128; i += NTHR) {
        int k = i >> 7, n = i & 127;
        sW1[k * W1STR + n] = __float2half_rn(W1[i]);
    }
    for (int i = tid; i < 128 * 96; i += NTHR) {
        int k = i / 96, n = i - k * 96;
        sW2[k * W2STR + n] = __float2half_rn(W2[i]);
    }
    if (tid < 128) sB1[tid] = b1[tid];
    else if (tid < 224) sB2[tid - 128] = b2[tid - 128];
    __syncthreads();

    // roles: wid 0-7 consumer grp0, 8-15 consumer grp1, 16-17 prod grp0, 18-19 prod grp1
    const bool is_prod = (wid >= 16);
    const int grp = is_prod ? ((wid - 16) >> 1) : (wid >> 3);
    // barrier ids per group: FULL0, FULL1, EMPTY0, EMPTY1, C
    const int bFULL  = 1 + grp * 5;       // +buf
    const int bEMPTY = 3 + grp * 5;       // +buf
    const int bC     = 5 + grp * 5;
    const uint32_t xBase = (uint32_t)(grp * 2 * XBUFB);
    int* gDst = sDst + grp * 128;

    const int tstart = blockIdx.x * 2 + grp;
    const int gstride = gridDim.x * 2;

    if (is_prod) {
        // ========= PRODUCER: 2 warps/group, 4 threads/edge, 4 passes of 16 edges ======
        const int ptid = tid - 512 - grp * 64;   // 0..63
        const int pe0  = ptid >> 2;              // 0..15
        const int s    = ptid & 3;               // quarter
        int i = 0;
        for (int t = tstart; t < n_tiles; t += gstride, i++) {
            const int buf = i & 1;
            if (i >= 2) BAR_SYNC(bEMPTY + buf, 320);
            __half* X = (__half*)(dyn + xBase + buf * XBUFB);
            const int base = t * ET;
            #pragma unroll
            for (int pass = 0; pass < 4; pass++) {
                const int pe = pass * 16 + pe0;
                const int e  = base + pe;
                const int ec = (e < E) ? e : (E - 1);
                const int srcn = ei[ec], dstn = ei[E + ec];
                if (s == 0) gDst[buf * ET + pe] = dstn;
                float4 rk[4];
                #pragma unroll
                for (int k = 0; k < 4; k++) rk[k] = *(const float4*)(rot + (size_t)ec * 16 + k * 4);
                const int rb = pe * XSTR;
                float tmp[8], in[8];
                *(float4*)(tmp)     = *(const float4*)(xs + (size_t)dstn * 32 + s * 8);
                *(float4*)(tmp + 4) = *(const float4*)(xs + (size_t)dstn * 32 + s * 8 + 4);
                wr8h(X, rb + s * 8, tmp);
                *(float4*)(tmp)     = *(const float4*)(xs + (size_t)srcn * 32 + s * 8);
                *(float4*)(tmp + 4) = *(const float4*)(xs + (size_t)srcn * 32 + s * 8 + 4);
                wr8h(X, rb + 96 + s * 8, tmp);
                #pragma unroll
                for (int jj = 0; jj < 2; jj++) {
                    const int j = 2 * s + jj;
                    *(float4*)(in)     = *(const float4*)(xr + (size_t)dstn * 64 + j * 8);
                    *(float4*)(in + 4) = *(const float4*)(xr + (size_t)dstn * 64 + j * 8 + 4);
                    rot8(in, rk, tmp);
                    wr8h(X, rb + 32 + j * 8, tmp);
                    *(float4*)(in)     = *(const float4*)(xr + (size_t)srcn * 64 + j * 8);
                    *(float4*)(in + 4) = *(const float4*)(xr + (size_t)srcn * 64 + j * 8 + 4);
                    rot8(in, rk, tmp);
                    wr8h(X, rb + 128 + j * 8, tmp);
                }
                *(float4*)(tmp)     = *(const float4*)(dist + (size_t)ec * 64 + s * 16);
                *(float4*)(tmp + 4) = *(const float4*)(dist + (size_t)ec * 64 + s * 16 + 4);
                wr8h(X, rb + 192 + s * 16, tmp);
                *(float4*)(tmp)     = *(const float4*)(dist + (size_t)ec * 64 + s * 16 + 8);
                *(float4*)(tmp + 4) = *(const float4*)(dist + (size_t)ec * 64 + s * 16 + 12);
                wr8h(X, rb + 200 + s * 16, tmp);
            }
            BAR_ARRIVE(bFULL + buf, 320);
        }
    } else {
        // ========= CONSUMER: 8 warps/group, warp tile 32 x 32 over 64 rows ==========
        const int cw = wid - grp * 8;            // 0..7
        const int mw = cw >> 2, nw = cw & 3;     // mw: 0..1 (32-row chunks)
        const int lr = lane & 15, lc = (lane >> 4) << 3;
        const int gq = lane >> 2, tc = (lane & 3) * 2;
        const uint32_t w1B = sb + B_W1, w2B = sb + B_W2;
        const int c0   = nw * 24 + tc;
        const int kfix = (((c0 >= 32 ? c0 : c0 + 24) - 32) >> 1) & 3;

        int i = 0;
        for (int t = tstart; t < n_tiles; t += gstride, i++) {
            const int buf = i & 1;
            const int base = t * ET;
            const uint32_t xB = sb + xBase + buf * XBUFB;

            BAR_SYNC(bFULL + buf, 320);

            // ---------- GEMM1: 64 x 128 x 256 ----------
            float acc[2][4][4] = {};
            #pragma unroll 2
            for (int ks = 0; ks < 16; ks++) {
                const int k0 = ks * 16;
                uint32_t b[4][2];
                ldsm4t(w1B + (uint32_t)(((k0 + lr) * W1STR + nw * 32 + lc) * 2),
                       b[0][0], b[0][1], b[1][0], b[1][1]);
                ldsm4t(w1B + (uint32_t)(((k0 + lr) * W1STR + nw * 32 + 16 + lc) * 2),
                       b[2][0], b[2][1], b[3][0], b[3][1]);
                uint32_t A[2][4];
                #pragma unroll
                for (int mi = 0; mi < 2; mi++)
                    ldsm4(xB + (uint32_t)(((mw * 32 + mi * 16 + lr) * XSTR + k0 + lc) * 2),
                          A[mi][0], A[mi][1], A[mi][2], A[mi][3]);
                #pragma unroll
                for (int mi = 0; mi < 2; mi++)
                    #pragma unroll
                    for (int nt = 0; nt < 4; nt++)
                        mma16816(acc[mi][nt], A[mi], b[nt]);
            }
            BAR_SYNC(bC, 256);                   // G1 reads of X[buf] done

            // ---------- epilogue1: bias + silu -> H via stmatrix ----------
            {
                const uint32_t hB = xB;          // H overlays X[buf]
                const int tsel = lane >> 3, rowin = lane & 7;
                #pragma unroll
                for (int mi = 0; mi < 2; mi++) {
                    uint32_t pk[4][2];
                    #pragma unroll
                    for (int ni = 0; ni < 4; ni++) {
                        const int c = nw * 32 + ni * 8 + tc;
                        float2 bb = *(const float2*)(sB1 + c);
                        float v[4];
                        v[0] = acc[mi][ni][0] + bb.x;  v[1] = acc[mi][ni][1] + bb.y;
                        v[2] = acc[mi][ni][2] + bb.x;  v[3] = acc[mi][ni][3] + bb.y;
                        #pragma unroll
                        for (int q = 0; q < 4; q++) v[q] = v[q] / (1.f + __expf(-v[q]));
                        __half h0 = __float2half_rn(v[0]), h1 = __float2half_rn(v[1]);
                        __half h2 = __float2half_rn(v[2]), h3 = __float2half_rn(v[3]);
                        pk[ni][0] = (uint32_t)__half_as_ushort(h0) | ((uint32_t)__half_as_ushort(h1) << 16);
                        pk[ni][1] = (uint32_t)__half_as_ushort(h2) | ((uint32_t)__half_as_ushort(h3) << 16);
                    }
                    #pragma unroll
                    for (int np = 0; np < 2; np++) {
                        const int ni_t = np * 2 + (tsel >> 1);
                        const int rh_t = tsel & 1;
                        const int row  = mw * 32 + mi * 16 + rh_t * 8 + rowin;
                        const int col  = nw * 32 + ni_t * 8;
                        uint32_t addr = hB + (uint32_t)((row * HSTR + col) * 2);
                        stsm4(addr, pk[np*2][0], pk[np*2][1], pk[np*2+1][0], pk[np*2+1][1]);
                    }
                }
            }
            BAR_SYNC(bC, 256);                   // H visible

            // ---------- GEMM2: 64 x 96 x 128 ----------
            float acc2[2][3][4] = {};
            #pragma unroll 2
            for (int ks = 0; ks < 8; ks++) {
                const int k0 = ks * 16;
                uint32_t b[3][2];
                ldsm4t(w2B + (uint32_t)(((k0 + lr) * W2STR + nw * 24 + lc) * 2),
                       b[0][0], b[0][1], b[1][0], b[1][1]);
                ldsm2t(w2B + (uint32_t)(((k0 + lr) * W2STR + nw * 24 + 16) * 2),
                       b[2][0], b[2][1]);
                uint32_t A[2][4];
                #pragma unroll
                for (int mi = 0; mi < 2; mi++)
                    ldsm4(xB + (uint32_t)(((mw * 32 + mi * 16 + lr) * HSTR + k0 + lc) * 2),
                          A[mi][0], A[mi][1], A[mi][2], A[mi][3]);
                #pragma unroll
                for (int mi = 0; mi < 2; mi++)
                    #pragma unroll
                    for (int nt = 0; nt < 3; nt++)
                        mma16816(acc2[mi][nt], A[mi], b[nt]);
            }

            // ---------- epilogue2: bias + forward rotate (hoisted R) + scatter ------
            #pragma unroll
            for (int mi = 0; mi < 2; mi++) {
                const int rr = mw * 32 + mi * 16 + gq;
                #pragma unroll
                for (int rh = 0; rh < 2; rh++) {
                    const int r = rr + rh * 8;
                    const int e = base + r;
                    if (e < E) {
                        const int nidx = gDst[buf * ET + r];
                        float4 R;
                        if (c0 + 16 >= 32)
                            R = *(const float4*)(rot + (size_t)e * 16 + kfix * 4);
                        #pragma unroll
                        for (int ni = 0; ni < 3; ni++) {
                            const int c = nw * 24 + ni * 8 + tc;
                            float2 bb = *(const float2*)(sB2 + c);
                            float m0 = acc2[mi][ni][rh*2]   + bb.x;
                            float m1 = acc2[mi][ni][rh*2+1] + bb.y;
                            if (c < 32) {
                                red2(outS + (size_t)nidx * 32 + c, m0, m1);
                            } else {
                                red2(outR + (size_t)nidx * 64 + (c - 32),
                                     m0 * R.x + m1 * R.z, m0 * R.y + m1 * R.w);
                            }
                        }
                    }
                }
            }
            BAR_ARRIVE(bEMPTY + buf, 320);
        }
    }
}

extern "C" void kernel_launch(void* const* d_in, const int* in_sizes, int n_in,
                              void* d_out, int out_size)
{
    const float* xs   = (const float*)d_in[0];
    const float* xr   = (const float*)d_in[1];
    const int*   ei   = (const int*)  d_in[2];
    const float* dist = (const float*)d_in[3];
    const float* rot  = (const float*)d_in[4];
    const float* W1   = (const float*)d_in[5];
    const float* b1   = (const float*)d_in[6];
    const float* W2   = (const float*)d_in[7];
    const float* b2   = (const float*)d_in[8];

    const int N = in_sizes[0] / 32;
    const int E = in_sizes[2] / 2;
    const int n_tiles = (E + ET - 1) / ET;

    float* outS = (float*)d_out;
    float* outR = outS + (size_t)N * 32;

    cudaMemsetAsync(d_out, 0, (size_t)out_size * sizeof(float), 0);
    cudaFuncSetAttribute(eq_main, cudaFuncAttributeMaxDynamicSharedMemorySize, SMEMB);
    int grid = (n_tiles + 1) / 2 < 148 ? (n_tiles + 1) / 2 : 148;
    eq_main<<<grid, NTHR, SMEMB>>>(xs, xr, ei, dist, rot, W1, b1, W2, b2,
                                   outS, outR, E, n_tiles);
}